// round 13
// baseline (speedup 1.0000x reference)
#include <cuda_runtime.h>
#include <cuda_fp16.h>
#include <cstdint>

// Problem constants: N=100000, E=1600000, D=128, H=256, C=40
#define NN 100000
#define EE 1600000
#define DD 128
#define HH 256
#define CC 40

// ---------------- scratch (static device globals) ---------------------------
__device__ __half g_aF[(size_t)NN * HH];   // rst (GEMM input)
__device__ __half g_tF[(size_t)NN * HH];   // mid / x-fp16 staging
__device__ __half g_hF[(size_t)NN * HH];   // layer out
#define W_TOT (32768 + 65536 + 65536 + 65536 + 10240)
__device__ __half g_wH[W_TOT], g_wL[W_TOT];
__device__ int  g_rowstart[NN + 1];
__device__ int  g_cursor[NN];
__device__ int  g_csr[EE];

// ---------------- CSR build ------------------------------------------------
__global__ void hist_kernel(const int* __restrict__ dst, int* __restrict__ cnt, int e) {
    int i = blockIdx.x * blockDim.x + threadIdx.x;
    if (i < e) atomicAdd(&cnt[dst[i]], 1);
}

__global__ void scan_kernel(int* __restrict__ cnt_cursor, int* __restrict__ row_start, int n) {
    __shared__ int wsum[32];
    __shared__ int carry;
    const int tid = threadIdx.x;
    const int lane = tid & 31;
    const int wid = tid >> 5;
    if (tid == 0) carry = 0;
    __syncthreads();
    for (int base = 0; base < n; base += 1024) {
        int i = base + tid;
        int v = (i < n) ? cnt_cursor[i] : 0;
        int x = v;
        #pragma unroll
        for (int o = 1; o < 32; o <<= 1) {
            int y = __shfl_up_sync(0xffffffffu, x, o);
            if (lane >= o) x += y;
        }
        if (lane == 31) wsum[wid] = x;
        __syncthreads();
        if (wid == 0) {
            int wv = wsum[lane];
            #pragma unroll
            for (int o = 1; o < 32; o <<= 1) {
                int y = __shfl_up_sync(0xffffffffu, wv, o);
                if (lane >= o) wv += y;
            }
            wsum[lane] = wv;
        }
        __syncthreads();
        int excl = x - v + (wid ? wsum[wid - 1] : 0) + carry;
        if (i < n) { row_start[i] = excl; cnt_cursor[i] = excl; }
        if (i == n - 1) row_start[n] = excl + v;
        __syncthreads();
        if (tid == 0) carry += wsum[31];
        __syncthreads();
    }
}

__global__ void fill_kernel(const int* __restrict__ src, const int* __restrict__ dst,
                            int* __restrict__ cursor, int* __restrict__ csr, int e) {
    int i = blockIdx.x * blockDim.x + threadIdx.x;
    if (i < e) {
        int p = atomicAdd(&cursor[dst[i]], 1);
        csr[p] = src[i];
    }
}

// ---------------- fp16 helpers ----------------------------------------------
__device__ __forceinline__ uint32_t packh(__half a, __half b) {
    __half2 h = __halves2half2(a, b);
    return *(uint32_t*)&h;
}
__device__ __forceinline__ float2 unpk_h2(uint32_t u) {
    __half2 h = *(__half2*)&u;
    return __half22float2(h);
}
__device__ __forceinline__ void wsplit_pair(float v0, float v1, uint32_t& hu, uint32_t& lu) {
    __half h0 = __float2half_rn(v0), h1 = __float2half_rn(v1);
    __half l0 = __float2half_rn(v0 - __half2float(h0));
    __half l1 = __float2half_rn(v1 - __half2float(h1));
    hu = packh(h0, h1); lu = packh(l0, l1);
}

// Merged weight splitter: all 5 matrices in one launch (hi+lo planes).
__global__ void split_all_kernel(
    const float* __restrict__ w1a, const float* __restrict__ w1b,
    const float* __restrict__ w2a, const float* __restrict__ w2b,
    const float* __restrict__ fcw,
    __half* __restrict__ dh, __half* __restrict__ dl)
{
    int i = blockIdx.x * blockDim.x + threadIdx.x;   // vec4 index
    int i4 = i * 4;
    if (i4 >= W_TOT) return;
    const float* s; int off;
    if      (i4 < 32768)  { s = w1a; off = i4; }
    else if (i4 < 98304)  { s = w1b; off = i4 - 32768; }
    else if (i4 < 163840) { s = w2a; off = i4 - 98304; }
    else if (i4 < 229376) { s = w2b; off = i4 - 163840; }
    else                  { s = fcw; off = i4 - 229376; }
    float4 v = *(const float4*)(s + off);
    uint2 hi, lo;
    wsplit_pair(v.x, v.y, hi.x, lo.x);
    wsplit_pair(v.z, v.w, hi.y, lo.y);
    ((uint2*)dh)[i] = hi;
    ((uint2*)dl)[i] = lo;
}

// fp32 -> fp16 bulk convert (cnt4 = float4 count)
__global__ void f2h_kernel(const float4* __restrict__ src, __half* __restrict__ dst, int cnt4) {
    int i = blockIdx.x * blockDim.x + threadIdx.x;
    if (i < cnt4) {
        float4 v = src[i];
        uint2 o;
        o.x = packh(__float2half_rn(v.x), __float2half_rn(v.y));
        o.y = packh(__float2half_rn(v.z), __float2half_rn(v.w));
        ((uint2*)dst)[i] = o;
    }
}

// ---------------- aggregation (gather, warp/node, fp16 I/O) ------------------
__global__ __launch_bounds__(256) void agg_h128(
    const __half* __restrict__ iF, const int* __restrict__ rs,
    const int* __restrict__ csr, const float* __restrict__ eps,
    __half* __restrict__ oF, int n)
{
    int w = (blockIdx.x * 256 + threadIdx.x) >> 5;
    if (w >= n) return;
    int lane = threadIdx.x & 31;
    float s = 1.0f + *eps;
    float acc[4];
    {
        uint2 u = ((const uint2*)(iF + (size_t)w * 128))[lane];
        float2 f0 = unpk_h2(u.x), f1 = unpk_h2(u.y);
        acc[0] = f0.x * s; acc[1] = f0.y * s; acc[2] = f1.x * s; acc[3] = f1.y * s;
    }
    int e0 = rs[w], e1 = rs[w + 1];
    for (int e = e0; e < e1; e++) {
        uint2 u = ((const uint2*)(iF + (size_t)csr[e] * 128))[lane];
        float2 f0 = unpk_h2(u.x), f1 = unpk_h2(u.y);
        acc[0] += f0.x; acc[1] += f0.y; acc[2] += f1.x; acc[3] += f1.y;
    }
    uint2 o;
    o.x = packh(__float2half_rn(acc[0]), __float2half_rn(acc[1]));
    o.y = packh(__float2half_rn(acc[2]), __float2half_rn(acc[3]));
    *(uint2*)((uint32_t*)oF + (size_t)w * 64 + lane * 2) = o;
}

__global__ __launch_bounds__(256) void agg_h256(
    const __half* __restrict__ iF, const int* __restrict__ rs,
    const int* __restrict__ csr, const float* __restrict__ eps,
    __half* __restrict__ oF, int n)
{
    int w = (blockIdx.x * 256 + threadIdx.x) >> 5;
    if (w >= n) return;
    int lane = threadIdx.x & 31;
    float s = 1.0f + *eps;
    float acc[8];
    {
        uint4 hv = ((const uint4*)(iF + (size_t)w * 256))[lane];
        const uint32_t* hp = (const uint32_t*)&hv;
        #pragma unroll
        for (int j = 0; j < 4; j++) {
            float2 f = unpk_h2(hp[j]);
            acc[2 * j] = f.x * s; acc[2 * j + 1] = f.y * s;
        }
    }
    int e0 = rs[w], e1 = rs[w + 1];
    for (int e = e0; e < e1; e++) {
        uint4 hv = ((const uint4*)(iF + (size_t)csr[e] * 256))[lane];
        const uint32_t* hp = (const uint32_t*)&hv;
        #pragma unroll
        for (int j = 0; j < 4; j++) {
            float2 f = unpk_h2(hp[j]);
            acc[2 * j] += f.x; acc[2 * j + 1] += f.y;
        }
    }
    uint4 o;
    o.x = packh(__float2half_rn(acc[0]), __float2half_rn(acc[1]));
    o.y = packh(__float2half_rn(acc[2]), __float2half_rn(acc[3]));
    o.z = packh(__float2half_rn(acc[4]), __float2half_rn(acc[5]));
    o.w = packh(__float2half_rn(acc[6]), __float2half_rn(acc[7]));
    *(uint4*)((uint32_t*)oF + (size_t)w * 128 + lane * 4) = o;
}

// ---------------- mma.sync helpers ------------------------------------------
__device__ __forceinline__ void ldsm4(uint32_t* r, uint32_t addr) {
    asm volatile("ldmatrix.sync.aligned.m8n8.x4.shared.b16 {%0,%1,%2,%3}, [%4];\n"
        : "=r"(r[0]), "=r"(r[1]), "=r"(r[2]), "=r"(r[3]) : "r"(addr));
}
__device__ __forceinline__ void ldsm4t(uint32_t* r, uint32_t addr) {
    asm volatile("ldmatrix.sync.aligned.m8n8.x4.trans.shared.b16 {%0,%1,%2,%3}, [%4];\n"
        : "=r"(r[0]), "=r"(r[1]), "=r"(r[2]), "=r"(r[3]) : "r"(addr));
}
__device__ __forceinline__ void mma16816(float* c, const uint32_t* a, const uint32_t* b) {
    asm volatile("mma.sync.aligned.m16n8k16.row.col.f32.f16.f16.f32 "
        "{%0,%1,%2,%3}, {%4,%5,%6,%7}, {%8,%9}, {%0,%1,%2,%3};\n"
        : "+f"(c[0]), "+f"(c[1]), "+f"(c[2]), "+f"(c[3])
        : "r"(a[0]), "r"(a[1]), "r"(a[2]), "r"(a[3]), "r"(b[0]), "r"(b[1]));
}
__device__ __forceinline__ void cp16(uint32_t daddr, const void* gptr, int srcsize) {
    asm volatile("cp.async.ca.shared.global [%0], [%1], 16, %2;"
                 :: "r"(daddr), "l"(gptr), "r"(srcsize));
}
#define CP_COMMIT() asm volatile("cp.async.commit_group;" ::: "memory")
template <int NWAIT>
__device__ __forceinline__ void cp_wait() {
    asm volatile("cp.async.wait_group %0;" :: "n"(NWAIT) : "memory");
}
__device__ __forceinline__ uint32_t smem_u32(const void* p) {
    uint32_t a;
    asm("{ .reg .u64 t; cvta.to.shared.u64 t, %1; cvt.u32.u64 %0, t; }" : "=r"(a) : "l"(p));
    return a;
}

// ---------------- fp16 tensor GEMM -------------------------------------------
// C[n,M] = act(A_f16[n,K] @ W[K,M] (+bias)); K%32==0.
// W = W_hi (WLO=false) or W_hi + W_lo (WLO=true, 2 mma products).
// CTA tile 128 x BN (BN = NWCOL*32); 3-stage cp.async ring, 1 barrier/chunk.
template <int NWCOL, bool WLO, bool RELU, bool BIAS, bool OUTHALF>
__global__ __launch_bounds__(256, 2) void gemm_hs(
    const __half* __restrict__ A,
    const __half* __restrict__ WH, const __half* __restrict__ WL,
    const float* __restrict__ bias, float* __restrict__ Cf,
    __half* __restrict__ Ch,
    int n, int K, int M)
{
    constexpr int BN    = NWCOL * 32;
    constexpr int MROWS = 8 / NWCOL;          // warp rows (2 or 4)
    constexpr int WTM   = 128 / MROWS;        // warp tile m (64 or 32)
    constexpr int MT    = WTM / 16;           // m16 tiles per warp (4 or 2)
    constexpr int SA    = 40;
    constexpr int SB    = BN + 8;
    constexpr int APL   = 128 * SA * 2;
    constexpr int BPL   = 32 * SB * 2;
    constexpr int NBPL  = WLO ? 2 : 1;
    constexpr int STAGE = APL + NBPL * BPL;
    constexpr int BCH   = BN / 8;             // cp16 per B row
    constexpr int BRPP  = 256 / BCH;          // B rows per pass
    constexpr int BPASS = 32 / BRPP;          // passes

    extern __shared__ char smem[];
    const uint32_t sbase = smem_u32(smem);
    const int tid = threadIdx.x, warp = tid >> 5, lane = tid & 31;
    const int wm = (warp % MROWS) * WTM;
    const int wn = (warp / MROWS) * 32;
    const int m0 = blockIdx.x * 128;
    const int n0 = blockIdx.y * BN;
    const int NC = K >> 5;

    float acc[MT][4][4];
    #pragma unroll
    for (int i = 0; i < MT; i++)
        #pragma unroll
        for (int j = 0; j < 4; j++)
            #pragma unroll
            for (int q = 0; q < 4; q++) acc[i][j][q] = 0.f;

    const int arow = tid >> 2, ach = tid & 3;
    const int brow = tid / BCH, bch = tid % BCH;
    auto load_chunk = [&](int c, int b) {
        uint32_t st = sbase + b * STAGE;
        int k0 = c * 32;
        #pragma unroll
        for (int r = 0; r < 2; r++) {
            int rr = arow + r * 64;
            int g = m0 + rr;
            int sz = (g < n) ? 16 : 0;
            size_t go = (size_t)(g < n ? g : 0) * K + k0 + ach * 8;
            cp16(st + rr * (SA * 2) + ach * 16, A + go, sz);
        }
        #pragma unroll
        for (int r = 0; r < BPASS; r++) {
            int rr = brow + r * BRPP;
            int gm = n0 + bch * 8;
            int sz = (gm + 8 <= M) ? 16 : 0;
            size_t go = (size_t)(k0 + rr) * M + (gm + 8 <= M ? gm : 0);
            uint32_t db = st + APL + rr * (SB * 2) + bch * 16;
            cp16(db, WH + go, sz);
            if (WLO) cp16(db + BPL, WL + go, sz);
        }
    };

    const int aLm = lane & 15, aLk = (lane >> 4) << 3;
    const int bLk = lane & 15, bLn = (lane >> 4) << 3;

    auto compute = [&](int b) {
        uint32_t pA  = sbase + b * STAGE;
        uint32_t pBH = pA + APL;
        uint32_t pBL = pBH + BPL;
        #pragma unroll
        for (int ks = 0; ks < 32; ks += 16) {
            uint32_t af[MT][4];
            #pragma unroll
            for (int mt = 0; mt < MT; mt++) {
                uint32_t off = (uint32_t)((wm + mt * 16 + aLm) * SA + ks + aLk) * 2;
                ldsm4(af[mt], pA + off);
            }
            #pragma unroll
            for (int ng = 0; ng < 2; ng++) {
                uint32_t bfH[4], bfL[4];
                uint32_t off = (uint32_t)((ks + bLk) * SB + wn + ng * 16 + bLn) * 2;
                ldsm4t(bfH, pBH + off);
                if (WLO) ldsm4t(bfL, pBL + off);
                #pragma unroll
                for (int half_ = 0; half_ < 2; half_++) {
                    int nb = ng * 2 + half_;
                    #pragma unroll
                    for (int mt = 0; mt < MT; mt++) {
                        mma16816(acc[mt][nb], af[mt], &bfH[half_ * 2]);
                        if (WLO) mma16816(acc[mt][nb], af[mt], &bfL[half_ * 2]);
                    }
                }
            }
        }
    };

    // 3-stage pipeline, one barrier per chunk
    load_chunk(0, 0); CP_COMMIT();
    load_chunk(1, 1); CP_COMMIT();
    for (int c = 0; c < NC; c++) {
        cp_wait<1>();
        __syncthreads();
        if (c + 2 < NC) load_chunk(c + 2, (c + 2) % 3);
        CP_COMMIT();
        compute(c % 3);
    }

    // epilogue: c0:(r,c) c1:(r,c+1) c2:(r+8,c) c3:(r+8,c+1)
    #pragma unroll
    for (int mt = 0; mt < MT; mt++)
        #pragma unroll
        for (int nb = 0; nb < 4; nb++) {
            int row = m0 + wm + mt * 16 + (lane >> 2);
            int col = n0 + wn + nb * 8 + (lane & 3) * 2;
            if (col >= M) continue;
            float v0 = acc[mt][nb][0], v1 = acc[mt][nb][1];
            float v2 = acc[mt][nb][2], v3 = acc[mt][nb][3];
            if (BIAS) {
                float b0 = bias[col], b1 = bias[col + 1];
                v0 += b0; v1 += b1; v2 += b0; v3 += b1;
            }
            if (RELU) {
                v0 = fmaxf(v0, 0.f); v1 = fmaxf(v1, 0.f);
                v2 = fmaxf(v2, 0.f); v3 = fmaxf(v3, 0.f);
            }
            if (OUTHALF) {
                if (row < n)
                    ((uint32_t*)Ch)[((size_t)row * M + col) >> 1] =
                        packh(__float2half_rn(v0), __float2half_rn(v1));
                if (row + 8 < n)
                    ((uint32_t*)Ch)[((size_t)(row + 8) * M + col) >> 1] =
                        packh(__float2half_rn(v2), __float2half_rn(v3));
            } else {
                if (row < n)
                    *(float2*)(Cf + (size_t)row * M + col) = make_float2(v0, v1);
                if (row + 8 < n)
                    *(float2*)(Cf + (size_t)(row + 8) * M + col) = make_float2(v2, v3);
            }
        }
}

static constexpr int GSMEM4 = 3 * (128 * 40 * 2 + 1 * (32 * 136 * 2));  // 56832 (hi-only)
static constexpr int GSMEM2 = 3 * (128 * 40 * 2 + 2 * (32 * 72 * 2));   // 58368 (hi+lo, BN=64)

// ---------------- launch ----------------------------------------------------
extern "C" void kernel_launch(void* const* d_in, const int* in_sizes, int n_in,
                              void* d_out, int out_size) {
    const float* x    = (const float*)d_in[0];
    const int*   src  = (const int*)d_in[1];
    const int*   dst  = (const int*)d_in[2];
    const float* eps1 = (const float*)d_in[3];
    const float* w1a  = (const float*)d_in[4];
    const float* w1b  = (const float*)d_in[5];
    const float* eps2 = (const float*)d_in[6];
    const float* w2a  = (const float*)d_in[7];
    const float* w2b  = (const float*)d_in[8];
    const float* fcw  = (const float*)d_in[9];
    const float* fcb  = (const float*)d_in[10];
    float* out = (float*)d_out;

    const int n = in_sizes[0] / DD;   // 100000
    const int e = in_sizes[1];        // 1600000

    __half *aF, *tF, *hF, *wH, *wL;
    int *rs, *cur, *csr;
    cudaGetSymbolAddress((void**)&aF, g_aF);
    cudaGetSymbolAddress((void**)&tF, g_tF);
    cudaGetSymbolAddress((void**)&hF, g_hF);
    cudaGetSymbolAddress((void**)&wH, g_wH);
    cudaGetSymbolAddress((void**)&wL, g_wL);
    cudaGetSymbolAddress((void**)&rs,  g_rowstart);
    cudaGetSymbolAddress((void**)&cur, g_cursor);
    cudaGetSymbolAddress((void**)&csr, g_csr);

    cudaFuncSetAttribute(gemm_hs<4, false, true,  false, true >,
                         cudaFuncAttributeMaxDynamicSharedMemorySize, GSMEM4);
    cudaFuncSetAttribute(gemm_hs<2, true,  false, true,  false>,
                         cudaFuncAttributeMaxDynamicSharedMemorySize, GSMEM2);

    // weight offsets in split weight buffer
    const int O1A = 0, O1B = 32768, O2A = 98304, O2B = 163840, OFC = 229376;

    // CSR build (dst-grouped)
    cudaMemsetAsync(cur, 0, (size_t)n * sizeof(int));
    int eb = (e + 255) / 256;
    hist_kernel<<<eb, 256>>>(dst, cur, e);
    scan_kernel<<<1, 1024>>>(cur, rs, n);
    fill_kernel<<<eb, 256>>>(src, dst, cur, csr, e);

    // one-shot conversions
    split_all_kernel<<<(W_TOT / 4 + 255) / 256, 256>>>(w1a, w1b, w2a, w2b, fcw, wH, wL);
    f2h_kernel<<<(n * DD / 4 + 255) / 256, 256>>>((const float4*)x, tF, n * DD / 4);

    const int aggBlocks = (n + 7) / 8;
    const int gm = (n + 127) / 128;
    dim3 gFull(gm, HH / 128);   // (782, 2)
    dim3 gFc(gm, 1);

    // Layer 1  (x-fp16 staged in tF; consumed by agg before G1 overwrites tF)
    agg_h128<<<aggBlocks, 256>>>(tF, rs, csr, eps1, aF, n);
    gemm_hs<4, false, true, false, true><<<gFull, 256, GSMEM4>>>(
        aF, wH + O1A, nullptr, nullptr, nullptr, tF, n, DD, HH);
    gemm_hs<4, false, true, false, true><<<gFull, 256, GSMEM4>>>(
        tF, wH + O1B, nullptr, nullptr, nullptr, hF, n, HH, HH);
    // Layer 2
    agg_h256<<<aggBlocks, 256>>>(hF, rs, csr, eps2, aF, n);
    gemm_hs<4, false, true, false, true><<<gFull, 256, GSMEM4>>>(
        aF, wH + O2A, nullptr, nullptr, nullptr, tF, n, HH, HH);
    gemm_hs<4, false, true, false, true><<<gFull, 256, GSMEM4>>>(
        tF, wH + O2B, nullptr, nullptr, nullptr, hF, n, HH, HH);
    // Classifier (BN=64, W hi+lo for extra final precision, fp32 out, bias)
    gemm_hs<2, true, false, true, false><<<gFc, 256, GSMEM2>>>(
        hF, wH + OFC, wL + OFC, fcb, out, nullptr, n, HH, CC);
}

// round 16
// speedup vs baseline: 1.4486x; 1.4486x over previous
#include <cuda_runtime.h>
#include <cuda_fp16.h>
#include <cstdint>

// Problem constants: N=100000, E=1600000, D=128, H=256, C=40
#define NN 100000
#define EE 1600000
#define DD 128
#define HH 256
#define CC 40

// ---------------- scratch (static device globals) ---------------------------
__device__ __half g_aF[(size_t)NN * HH];   // rst (GEMM input)
__device__ __half g_tF[(size_t)NN * HH];   // mid / x-fp16 staging
__device__ __half g_hF[(size_t)NN * HH];   // layer out
#define W_TOT (32768 + 65536 + 65536 + 65536 + 10240)
__device__ __half g_wH[W_TOT], g_wL[W_TOT];
__device__ int  g_rowstart[NN + 1];
__device__ int  g_cursor[NN];
__device__ int  g_csr[EE];

// ---------------- CSR build ------------------------------------------------
__global__ void hist_kernel(const int* __restrict__ dst, int* __restrict__ cnt, int e) {
    int i = blockIdx.x * blockDim.x + threadIdx.x;
    if (i < e) atomicAdd(&cnt[dst[i]], 1);
}

__global__ void scan_kernel(int* __restrict__ cnt_cursor, int* __restrict__ row_start, int n) {
    __shared__ int wsum[32];
    __shared__ int carry;
    const int tid = threadIdx.x;
    const int lane = tid & 31;
    const int wid = tid >> 5;
    if (tid == 0) carry = 0;
    __syncthreads();
    for (int base = 0; base < n; base += 1024) {
        int i = base + tid;
        int v = (i < n) ? cnt_cursor[i] : 0;
        int x = v;
        #pragma unroll
        for (int o = 1; o < 32; o <<= 1) {
            int y = __shfl_up_sync(0xffffffffu, x, o);
            if (lane >= o) x += y;
        }
        if (lane == 31) wsum[wid] = x;
        __syncthreads();
        if (wid == 0) {
            int wv = wsum[lane];
            #pragma unroll
            for (int o = 1; o < 32; o <<= 1) {
                int y = __shfl_up_sync(0xffffffffu, wv, o);
                if (lane >= o) wv += y;
            }
            wsum[lane] = wv;
        }
        __syncthreads();
        int excl = x - v + (wid ? wsum[wid - 1] : 0) + carry;
        if (i < n) { row_start[i] = excl; cnt_cursor[i] = excl; }
        if (i == n - 1) row_start[n] = excl + v;
        __syncthreads();
        if (tid == 0) carry += wsum[31];
        __syncthreads();
    }
}

__global__ void fill_kernel(const int* __restrict__ src, const int* __restrict__ dst,
                            int* __restrict__ cursor, int* __restrict__ csr, int e) {
    int i = blockIdx.x * blockDim.x + threadIdx.x;
    if (i < e) {
        int p = atomicAdd(&cursor[dst[i]], 1);
        csr[p] = src[i];
    }
}

// ---------------- fp16 helpers ----------------------------------------------
__device__ __forceinline__ uint32_t packh(__half a, __half b) {
    __half2 h = __halves2half2(a, b);
    return *(uint32_t*)&h;
}
__device__ __forceinline__ float2 unpk_h2(uint32_t u) {
    __half2 h = *(__half2*)&u;
    return __half22float2(h);
}
__device__ __forceinline__ void wsplit_pair(float v0, float v1, uint32_t& hu, uint32_t& lu) {
    __half h0 = __float2half_rn(v0), h1 = __float2half_rn(v1);
    __half l0 = __float2half_rn(v0 - __half2float(h0));
    __half l1 = __float2half_rn(v1 - __half2float(h1));
    hu = packh(h0, h1); lu = packh(l0, l1);
}

// Merged weight splitter: all 5 matrices in one launch (hi+lo planes).
__global__ void split_all_kernel(
    const float* __restrict__ w1a, const float* __restrict__ w1b,
    const float* __restrict__ w2a, const float* __restrict__ w2b,
    const float* __restrict__ fcw,
    __half* __restrict__ dh, __half* __restrict__ dl)
{
    int i = blockIdx.x * blockDim.x + threadIdx.x;   // vec4 index
    int i4 = i * 4;
    if (i4 >= W_TOT) return;
    const float* s; int off;
    if      (i4 < 32768)  { s = w1a; off = i4; }
    else if (i4 < 98304)  { s = w1b; off = i4 - 32768; }
    else if (i4 < 163840) { s = w2a; off = i4 - 98304; }
    else if (i4 < 229376) { s = w2b; off = i4 - 163840; }
    else                  { s = fcw; off = i4 - 229376; }
    float4 v = *(const float4*)(s + off);
    uint2 hi, lo;
    wsplit_pair(v.x, v.y, hi.x, lo.x);
    wsplit_pair(v.z, v.w, hi.y, lo.y);
    ((uint2*)dh)[i] = hi;
    ((uint2*)dl)[i] = lo;
}

// fp32 -> fp16 bulk convert (cnt4 = float4 count)
__global__ void f2h_kernel(const float4* __restrict__ src, __half* __restrict__ dst, int cnt4) {
    int i = blockIdx.x * blockDim.x + threadIdx.x;
    if (i < cnt4) {
        float4 v = src[i];
        uint2 o;
        o.x = packh(__float2half_rn(v.x), __float2half_rn(v.y));
        o.y = packh(__float2half_rn(v.z), __float2half_rn(v.w));
        ((uint2*)dst)[i] = o;
    }
}

// ---------------- aggregation (gather, warp/node, fp16 I/O) ------------------
__global__ __launch_bounds__(256) void agg_h128(
    const __half* __restrict__ iF, const int* __restrict__ rs,
    const int* __restrict__ csr, const float* __restrict__ eps,
    __half* __restrict__ oF, int n)
{
    int w = (blockIdx.x * 256 + threadIdx.x) >> 5;
    if (w >= n) return;
    int lane = threadIdx.x & 31;
    float s = 1.0f + *eps;
    float acc[4];
    {
        uint2 u = ((const uint2*)(iF + (size_t)w * 128))[lane];
        float2 f0 = unpk_h2(u.x), f1 = unpk_h2(u.y);
        acc[0] = f0.x * s; acc[1] = f0.y * s; acc[2] = f1.x * s; acc[3] = f1.y * s;
    }
    int e0 = rs[w], e1 = rs[w + 1];
    for (int e = e0; e < e1; e++) {
        uint2 u = ((const uint2*)(iF + (size_t)csr[e] * 128))[lane];
        float2 f0 = unpk_h2(u.x), f1 = unpk_h2(u.y);
        acc[0] += f0.x; acc[1] += f0.y; acc[2] += f1.x; acc[3] += f1.y;
    }
    uint2 o;
    o.x = packh(__float2half_rn(acc[0]), __float2half_rn(acc[1]));
    o.y = packh(__float2half_rn(acc[2]), __float2half_rn(acc[3]));
    *(uint2*)((uint32_t*)oF + (size_t)w * 64 + lane * 2) = o;
}

__global__ __launch_bounds__(256) void agg_h256(
    const __half* __restrict__ iF, const int* __restrict__ rs,
    const int* __restrict__ csr, const float* __restrict__ eps,
    __half* __restrict__ oF, int n)
{
    int w = (blockIdx.x * 256 + threadIdx.x) >> 5;
    if (w >= n) return;
    int lane = threadIdx.x & 31;
    float s = 1.0f + *eps;
    float acc[8];
    {
        uint4 hv = ((const uint4*)(iF + (size_t)w * 256))[lane];
        const uint32_t* hp = (const uint32_t*)&hv;
        #pragma unroll
        for (int j = 0; j < 4; j++) {
            float2 f = unpk_h2(hp[j]);
            acc[2 * j] = f.x * s; acc[2 * j + 1] = f.y * s;
        }
    }
    int e0 = rs[w], e1 = rs[w + 1];
    for (int e = e0; e < e1; e++) {
        uint4 hv = ((const uint4*)(iF + (size_t)csr[e] * 256))[lane];
        const uint32_t* hp = (const uint32_t*)&hv;
        #pragma unroll
        for (int j = 0; j < 4; j++) {
            float2 f = unpk_h2(hp[j]);
            acc[2 * j] += f.x; acc[2 * j + 1] += f.y;
        }
    }
    uint4 o;
    o.x = packh(__float2half_rn(acc[0]), __float2half_rn(acc[1]));
    o.y = packh(__float2half_rn(acc[2]), __float2half_rn(acc[3]));
    o.z = packh(__float2half_rn(acc[4]), __float2half_rn(acc[5]));
    o.w = packh(__float2half_rn(acc[6]), __float2half_rn(acc[7]));
    *(uint4*)((uint32_t*)oF + (size_t)w * 128 + lane * 4) = o;
}

// ---------------- mma.sync helpers ------------------------------------------
__device__ __forceinline__ void ldsm4(uint32_t* r, uint32_t addr) {
    asm volatile("ldmatrix.sync.aligned.m8n8.x4.shared.b16 {%0,%1,%2,%3}, [%4];\n"
        : "=r"(r[0]), "=r"(r[1]), "=r"(r[2]), "=r"(r[3]) : "r"(addr));
}
__device__ __forceinline__ void ldsm4t(uint32_t* r, uint32_t addr) {
    asm volatile("ldmatrix.sync.aligned.m8n8.x4.trans.shared.b16 {%0,%1,%2,%3}, [%4];\n"
        : "=r"(r[0]), "=r"(r[1]), "=r"(r[2]), "=r"(r[3]) : "r"(addr));
}
__device__ __forceinline__ void mma16816(float* c, const uint32_t* a, const uint32_t* b) {
    asm volatile("mma.sync.aligned.m16n8k16.row.col.f32.f16.f16.f32 "
        "{%0,%1,%2,%3}, {%4,%5,%6,%7}, {%8,%9}, {%0,%1,%2,%3};\n"
        : "+f"(c[0]), "+f"(c[1]), "+f"(c[2]), "+f"(c[3])
        : "r"(a[0]), "r"(a[1]), "r"(a[2]), "r"(a[3]), "r"(b[0]), "r"(b[1]));
}
__device__ __forceinline__ void cp16(uint32_t daddr, const void* gptr, int srcsize) {
    asm volatile("cp.async.ca.shared.global [%0], [%1], 16, %2;"
                 :: "r"(daddr), "l"(gptr), "r"(srcsize));
}
#define CP_COMMIT() asm volatile("cp.async.commit_group;" ::: "memory")
template <int NWAIT>
__device__ __forceinline__ void cp_wait() {
    asm volatile("cp.async.wait_group %0;" :: "n"(NWAIT) : "memory");
}
__device__ __forceinline__ uint32_t smem_u32(const void* p) {
    uint32_t a;
    asm("{ .reg .u64 t; cvta.to.shared.u64 t, %1; cvt.u32.u64 %0, t; }" : "=r"(a) : "l"(p));
    return a;
}

// ---------------- fp16 tensor GEMM -------------------------------------------
// C[n,M] = act(A_f16[n,K] @ W[K,M] (+bias)); K%32==0.
// W = W_hi (WLO=false) or W_hi + W_lo (WLO=true, 2 mma products).
// CTA tile 128 x BN (BN = NWCOL*32).
// 4-stage cp.async ring, depth-3 prefetch, ONE barrier per K-chunk:
//   preload chunks 0..2; iter c: cp_wait<2> (chunk c done, c+1/c+2 in flight)
//   -> sync (publishes c; proves all warps done with c-1)
//   -> load chunk c+3 into slot (c+3)%4 == (c-1)%4 (free by the sync)
//   -> compute(c)
template <int NWCOL, bool WLO, bool RELU, bool BIAS, bool OUTHALF>
__global__ __launch_bounds__(256, 2) void gemm_hs(
    const __half* __restrict__ A,
    const __half* __restrict__ WH, const __half* __restrict__ WL,
    const float* __restrict__ bias, float* __restrict__ Cf,
    __half* __restrict__ Ch,
    int n, int K, int M)
{
    constexpr int BN    = NWCOL * 32;
    constexpr int MROWS = 8 / NWCOL;          // warp rows (2 or 4)
    constexpr int WTM   = 128 / MROWS;        // warp tile m (64 or 32)
    constexpr int MT    = WTM / 16;           // m16 tiles per warp (4 or 2)
    constexpr int SA    = 40;
    constexpr int SB    = BN + 8;
    constexpr int APL   = 128 * SA * 2;
    constexpr int BPL   = 32 * SB * 2;
    constexpr int NBPL  = WLO ? 2 : 1;
    constexpr int STAGE = APL + NBPL * BPL;
    constexpr int BCH   = BN / 8;             // cp16 per B row
    constexpr int BRPP  = 256 / BCH;          // B rows per pass
    constexpr int BPASS = 32 / BRPP;          // passes

    extern __shared__ char smem[];
    const uint32_t sbase = smem_u32(smem);
    const int tid = threadIdx.x, warp = tid >> 5, lane = tid & 31;
    const int wm = (warp % MROWS) * WTM;
    const int wn = (warp / MROWS) * 32;
    const int m0 = blockIdx.x * 128;
    const int n0 = blockIdx.y * BN;
    const int NC = K >> 5;

    float acc[MT][4][4];
    #pragma unroll
    for (int i = 0; i < MT; i++)
        #pragma unroll
        for (int j = 0; j < 4; j++)
            #pragma unroll
            for (int q = 0; q < 4; q++) acc[i][j][q] = 0.f;

    const int arow = tid >> 2, ach = tid & 3;
    const int brow = tid / BCH, bch = tid % BCH;
    auto load_chunk = [&](int c, int b) {
        uint32_t st = sbase + b * STAGE;
        int k0 = c * 32;
        #pragma unroll
        for (int r = 0; r < 2; r++) {
            int rr = arow + r * 64;
            int g = m0 + rr;
            int sz = (g < n) ? 16 : 0;
            size_t go = (size_t)(g < n ? g : 0) * K + k0 + ach * 8;
            cp16(st + rr * (SA * 2) + ach * 16, A + go, sz);
        }
        #pragma unroll
        for (int r = 0; r < BPASS; r++) {
            int rr = brow + r * BRPP;
            int gm = n0 + bch * 8;
            int sz = (gm + 8 <= M) ? 16 : 0;
            size_t go = (size_t)(k0 + rr) * M + (gm + 8 <= M ? gm : 0);
            uint32_t db = st + APL + rr * (SB * 2) + bch * 16;
            cp16(db, WH + go, sz);
            if (WLO) cp16(db + BPL, WL + go, sz);
        }
    };

    const int aLm = lane & 15, aLk = (lane >> 4) << 3;
    const int bLk = lane & 15, bLn = (lane >> 4) << 3;

    auto compute = [&](int b) {
        uint32_t pA  = sbase + b * STAGE;
        uint32_t pBH = pA + APL;
        uint32_t pBL = pBH + BPL;
        #pragma unroll
        for (int ks = 0; ks < 32; ks += 16) {
            uint32_t af[MT][4];
            #pragma unroll
            for (int mt = 0; mt < MT; mt++) {
                uint32_t off = (uint32_t)((wm + mt * 16 + aLm) * SA + ks + aLk) * 2;
                ldsm4(af[mt], pA + off);
            }
            #pragma unroll
            for (int ng = 0; ng < 2; ng++) {
                uint32_t bfH[4], bfL[4];
                uint32_t off = (uint32_t)((ks + bLk) * SB + wn + ng * 16 + bLn) * 2;
                ldsm4t(bfH, pBH + off);
                if (WLO) ldsm4t(bfL, pBL + off);
                #pragma unroll
                for (int half_ = 0; half_ < 2; half_++) {
                    int nb = ng * 2 + half_;
                    #pragma unroll
                    for (int mt = 0; mt < MT; mt++) {
                        mma16816(acc[mt][nb], af[mt], &bfH[half_ * 2]);
                        if (WLO) mma16816(acc[mt][nb], af[mt], &bfL[half_ * 2]);
                    }
                }
            }
        }
    };

    // 4-stage pipeline, depth-3 prefetch, one barrier per chunk
    load_chunk(0, 0); CP_COMMIT();
    load_chunk(1, 1); CP_COMMIT();
    load_chunk(2, 2); CP_COMMIT();
    for (int c = 0; c < NC; c++) {
        cp_wait<2>();            // chunk c complete; c+1, c+2 still in flight
        __syncthreads();
        if (c + 3 < NC) load_chunk(c + 3, (c + 3) & 3);
        CP_COMMIT();
        compute(c & 3);
    }

    // epilogue: c0:(r,c) c1:(r,c+1) c2:(r+8,c) c3:(r+8,c+1)
    #pragma unroll
    for (int mt = 0; mt < MT; mt++)
        #pragma unroll
        for (int nb = 0; nb < 4; nb++) {
            int row = m0 + wm + mt * 16 + (lane >> 2);
            int col = n0 + wn + nb * 8 + (lane & 3) * 2;
            if (col >= M) continue;
            float v0 = acc[mt][nb][0], v1 = acc[mt][nb][1];
            float v2 = acc[mt][nb][2], v3 = acc[mt][nb][3];
            if (BIAS) {
                float b0 = bias[col], b1 = bias[col + 1];
                v0 += b0; v1 += b1; v2 += b0; v3 += b1;
            }
            if (RELU) {
                v0 = fmaxf(v0, 0.f); v1 = fmaxf(v1, 0.f);
                v2 = fmaxf(v2, 0.f); v3 = fmaxf(v3, 0.f);
            }
            if (OUTHALF) {
                if (row < n)
                    ((uint32_t*)Ch)[((size_t)row * M + col) >> 1] =
                        packh(__float2half_rn(v0), __float2half_rn(v1));
                if (row + 8 < n)
                    ((uint32_t*)Ch)[((size_t)(row + 8) * M + col) >> 1] =
                        packh(__float2half_rn(v2), __float2half_rn(v3));
            } else {
                if (row < n)
                    *(float2*)(Cf + (size_t)row * M + col) = make_float2(v0, v1);
                if (row + 8 < n)
                    *(float2*)(Cf + (size_t)(row + 8) * M + col) = make_float2(v2, v3);
            }
        }
}

static constexpr int GSMEM4 = 4 * (128 * 40 * 2 + 1 * (32 * 136 * 2));  // 75776 (hi-only)
static constexpr int GSMEM2 = 4 * (128 * 40 * 2 + 2 * (32 * 72 * 2));   // 77824 (hi+lo, BN=64)

// ---------------- launch ----------------------------------------------------
extern "C" void kernel_launch(void* const* d_in, const int* in_sizes, int n_in,
                              void* d_out, int out_size) {
    const float* x    = (const float*)d_in[0];
    const int*   src  = (const int*)d_in[1];
    const int*   dst  = (const int*)d_in[2];
    const float* eps1 = (const float*)d_in[3];
    const float* w1a  = (const float*)d_in[4];
    const float* w1b  = (const float*)d_in[5];
    const float* eps2 = (const float*)d_in[6];
    const float* w2a  = (const float*)d_in[7];
    const float* w2b  = (const float*)d_in[8];
    const float* fcw  = (const float*)d_in[9];
    const float* fcb  = (const float*)d_in[10];
    float* out = (float*)d_out;

    const int n = in_sizes[0] / DD;   // 100000
    const int e = in_sizes[1];        // 1600000

    __half *aF, *tF, *hF, *wH, *wL;
    int *rs, *cur, *csr;
    cudaGetSymbolAddress((void**)&aF, g_aF);
    cudaGetSymbolAddress((void**)&tF, g_tF);
    cudaGetSymbolAddress((void**)&hF, g_hF);
    cudaGetSymbolAddress((void**)&wH, g_wH);
    cudaGetSymbolAddress((void**)&wL, g_wL);
    cudaGetSymbolAddress((void**)&rs,  g_rowstart);
    cudaGetSymbolAddress((void**)&cur, g_cursor);
    cudaGetSymbolAddress((void**)&csr, g_csr);

    cudaFuncSetAttribute(gemm_hs<4, false, true,  false, true >,
                         cudaFuncAttributeMaxDynamicSharedMemorySize, GSMEM4);
    cudaFuncSetAttribute(gemm_hs<2, true,  false, true,  false>,
                         cudaFuncAttributeMaxDynamicSharedMemorySize, GSMEM2);

    // weight offsets in split weight buffer
    const int O1A = 0, O1B = 32768, O2A = 98304, O2B = 163840, OFC = 229376;

    // CSR build (dst-grouped)
    cudaMemsetAsync(cur, 0, (size_t)n * sizeof(int));
    int eb = (e + 255) / 256;
    hist_kernel<<<eb, 256>>>(dst, cur, e);
    scan_kernel<<<1, 1024>>>(cur, rs, n);
    fill_kernel<<<eb, 256>>>(src, dst, cur, csr, e);

    // one-shot conversions
    split_all_kernel<<<(W_TOT / 4 + 255) / 256, 256>>>(w1a, w1b, w2a, w2b, fcw, wH, wL);
    f2h_kernel<<<(n * DD / 4 + 255) / 256, 256>>>((const float4*)x, tF, n * DD / 4);

    const int aggBlocks = (n + 7) / 8;
    const int gm = (n + 127) / 128;
    dim3 gFull(gm, HH / 128);   // (782, 2)
    dim3 gFc(gm, 1);

    // Layer 1  (x-fp16 staged in tF; consumed by agg before G1 overwrites tF)
    agg_h128<<<aggBlocks, 256>>>(tF, rs, csr, eps1, aF, n);
    gemm_hs<4, false, true, false, true><<<gFull, 256, GSMEM4>>>(
        aF, wH + O1A, nullptr, nullptr, nullptr, tF, n, DD, HH);
    gemm_hs<4, false, true, false, true><<<gFull, 256, GSMEM4>>>(
        tF, wH + O1B, nullptr, nullptr, nullptr, hF, n, HH, HH);
    // Layer 2
    agg_h256<<<aggBlocks, 256>>>(hF, rs, csr, eps2, aF, n);
    gemm_hs<4, false, true, false, true><<<gFull, 256, GSMEM4>>>(
        aF, wH + O2A, nullptr, nullptr, nullptr, tF, n, HH, HH);
    gemm_hs<4, false, true, false, true><<<gFull, 256, GSMEM4>>>(
        tF, wH + O2B, nullptr, nullptr, nullptr, hF, n, HH, HH);
    // Classifier (BN=64, W hi+lo for extra final precision, fp32 out, bias)
    gemm_hs<2, true, false, true, false><<<gFc, 256, GSMEM2>>>(
        hF, wH + OFC, wL + OFC, fcb, out, nullptr, n, HH, CC);
}